// round 2
// baseline (speedup 1.0000x reference)
#include <cuda_runtime.h>
#include <cuda_bf16.h>
#include <cstdint>

#define B_    16
#define T_    2048
#define D_    1024
#define TT_   2046
#define MW_   682
#define M_    (B_ * MW_)          // 10912
#define NMUT  64
#define NBIN  32
#define KCAT  (D_ + NMUT)         // 1088

// -------- device scratch (no allocations allowed) --------
__device__ float g_wt [D_ * D_];          // dense_w transposed [K][N]
__device__ float g_owt[D_ * NMUT];        // out_w transposed   [1024][64]
__device__ float g_bwt[KCAT * NBIN];      // bin_w transposed   [1088][32]
__device__ float g_wf [M_ * D_];          // word features      [M][1024]
__device__ float g_h  [M_ * D_];          // tanh hidden        [M][1024]
__device__ int   g_begin[M_];
__device__ int   g_cnt  [M_];

// ---------------------------------------------------------------------------
// 1) per-batch scan of word_starts -> word begin token + token count
// ---------------------------------------------------------------------------
__global__ void scan_kernel(const int* __restrict__ ws) {
    int b = blockIdx.x;
    const int* w = ws + b * TT_;
    __shared__ int partial[256];
    __shared__ int scnt[MW_];
    int tid = threadIdx.x;
    for (int i = tid; i < MW_; i += 256) scnt[i] = 0;

    int vals[8];
    int s = 0;
#pragma unroll
    for (int i = 0; i < 8; i++) {
        int t = tid * 8 + i;
        int v = (t < TT_) ? w[t] : 0;
        vals[i] = v; s += v;
    }
    partial[tid] = s;
    __syncthreads();
    // Hillis-Steele scan over 256 partials
    for (int off = 1; off < 256; off <<= 1) {
        int v = partial[tid];
        int add = (tid >= off) ? partial[tid - off] : 0;
        __syncthreads();
        partial[tid] = v + add;
        __syncthreads();
    }
    int run = (tid > 0) ? partial[tid - 1] : 0;
#pragma unroll
    for (int i = 0; i < 8; i++) {
        int t = tid * 8 + i;
        if (t < TT_) {
            run += vals[i];
            int seg = run - 1;
            if (seg >= 0 && seg < MW_) {
                if (vals[i]) g_begin[b * MW_ + seg] = t;
                atomicAdd(&scnt[seg], 1);
            }
        }
    }
    __syncthreads();
    for (int i = tid; i < MW_; i += 256) g_cnt[b * MW_ + i] = scnt[i];
}

// ---------------------------------------------------------------------------
// 2) word-feature segment sums (one block per word, float4 along D)
// ---------------------------------------------------------------------------
__global__ void wf_kernel(const float* __restrict__ feat) {
    int m = blockIdx.x;            // 0..M_-1
    int b = m / MW_;
    int tid = threadIdx.x;         // 256 threads -> 256 float4 = 1024 floats
    int cnt = g_cnt[m];
    float4* out = (float4*)(g_wf + (size_t)m * D_);
    if (cnt == 0) { out[tid] = make_float4(1.f, 1.f, 1.f, 1.f); return; }
    int t0 = g_begin[m];
    const float4* base = (const float4*)(feat + ((size_t)b * T_ + 1 + t0) * D_);
    float4 acc = base[tid];
    for (int i = 1; i < cnt; i++) {
        float4 v = base[(size_t)i * (D_ / 4) + tid];
        acc.x += v.x; acc.y += v.y; acc.z += v.z; acc.w += v.w;
    }
    out[tid] = acc;
}

// ---------------------------------------------------------------------------
// 3) transpose: out[c][r] = in[r][c]
// ---------------------------------------------------------------------------
__global__ void transpose_kernel(const float* __restrict__ in, float* __restrict__ out,
                                 int rows, int cols) {
    __shared__ float tile[32][33];
    int c = blockIdx.x * 32 + threadIdx.x;
    int rbase = blockIdx.y * 32;
    for (int i = 0; i < 32; i += 8) {
        int r = rbase + threadIdx.y + i;
        if (r < rows && c < cols) tile[threadIdx.y + i][threadIdx.x] = in[(size_t)r * cols + c];
    }
    __syncthreads();
    int oc = rbase + threadIdx.x;               // original row -> minor out dim
    int obase = blockIdx.x * 32;                // original col -> major out dim
    for (int i = 0; i < 32; i += 8) {
        int orow = obase + threadIdx.y + i;
        if (orow < cols && oc < rows) out[(size_t)orow * rows + oc] = tile[threadIdx.x][threadIdx.y + i];
    }
}

// ---------------------------------------------------------------------------
// 4) main GEMM: h = tanh(wf @ wt + bias), M=10912, N=K=1024
//    128x128 tile, BK=8, 256 threads, 8x8 micro (2x2 groups of 4x4)
// ---------------------------------------------------------------------------
__global__ __launch_bounds__(256, 2) void gemm_main(
    const float* __restrict__ A, const float* __restrict__ Bt,
    const float* __restrict__ bias, float* __restrict__ C, int M)
{
    const int K = 1024, N = 1024;
    __shared__ float As[8][132];   // +4 pad keeps 16B alignment, kills STS conflicts
    __shared__ float Bs[8][128];
    const int tid  = threadIdx.x;
    const int row0 = blockIdx.y * 128;
    const int col0 = blockIdx.x * 128;
    const int aRow = tid >> 1;            // (tid*4)/8
    const int aCol = (tid & 1) * 4;
    const int bRow = tid >> 5;            // (tid*4)/128
    const int bCol = (tid & 31) * 4;
    const int tr   = (tid >> 4) * 4;      // 0..60
    const int tc   = (tid & 15) * 4;      // 0..60

    float acc[8][8];
#pragma unroll
    for (int i = 0; i < 8; i++)
#pragma unroll
        for (int j = 0; j < 8; j++) acc[i][j] = 0.f;

    const bool aval = (row0 + aRow) < M;
    const float* Aptr = A + (size_t)(row0 + aRow) * K + aCol;
    const float* Bptr = Bt + (size_t)bRow * N + col0 + bCol;

    for (int k0 = 0; k0 < K; k0 += 8) {
        float4 av = aval ? *(const float4*)Aptr : make_float4(0.f, 0.f, 0.f, 0.f);
        Aptr += 8;
        As[aCol + 0][aRow] = av.x;
        As[aCol + 1][aRow] = av.y;
        As[aCol + 2][aRow] = av.z;
        As[aCol + 3][aRow] = av.w;
        float4 bv = *(const float4*)Bptr;
        Bptr += (size_t)8 * N;
        *(float4*)&Bs[bRow][bCol] = bv;
        __syncthreads();
#pragma unroll
        for (int kk = 0; kk < 8; kk++) {
            float ar[8], br[8];
            *(float4*)&ar[0] = *(const float4*)&As[kk][tr];
            *(float4*)&ar[4] = *(const float4*)&As[kk][tr + 64];
            *(float4*)&br[0] = *(const float4*)&Bs[kk][tc];
            *(float4*)&br[4] = *(const float4*)&Bs[kk][tc + 64];
#pragma unroll
            for (int i = 0; i < 8; i++)
#pragma unroll
                for (int j = 0; j < 8; j++)
                    acc[i][j] = fmaf(ar[i], br[j], acc[i][j]);
        }
        __syncthreads();
    }
    // epilogue: bias + tanh, float4 stores (fully coalesced across the warp)
#pragma unroll
    for (int ig = 0; ig < 2; ig++)
#pragma unroll
        for (int i = 0; i < 4; i++) {
            int r = row0 + tr + ig * 64 + i;
            if (r < M) {
#pragma unroll
                for (int jg = 0; jg < 2; jg++) {
                    int c = col0 + tc + jg * 64;
                    float4 o;
                    o.x = tanhf(acc[ig * 4 + i][jg * 4 + 0] + bias[c + 0]);
                    o.y = tanhf(acc[ig * 4 + i][jg * 4 + 1] + bias[c + 1]);
                    o.z = tanhf(acc[ig * 4 + i][jg * 4 + 2] + bias[c + 2]);
                    o.w = tanhf(acc[ig * 4 + i][jg * 4 + 3] + bias[c + 3]);
                    *(float4*)(C + (size_t)r * 1024 + c) = o;
                }
            }
        }
}

// ---------------------------------------------------------------------------
// 5) small GEMMs for the heads (CONCAT handles cat[logits64, h1024] virtually)
// ---------------------------------------------------------------------------
template <int BM, int BN, int BK, int TM, int TN, bool CONCAT>
__global__ void gemm_small(const float* __restrict__ A, const float* __restrict__ A2,
                           const float* __restrict__ Bt, const float* __restrict__ bias,
                           float* __restrict__ C, int M, int N, int K, int lda)
{
    constexpr int NT = (BM / TM) * (BN / TN);
    __shared__ float As[BM][BK];
    __shared__ float Bs[BK][BN];
    int tid  = threadIdx.x;
    int row0 = blockIdx.y * BM;
    int col0 = blockIdx.x * BN;
    float acc[TM][TN];
#pragma unroll
    for (int i = 0; i < TM; i++)
#pragma unroll
        for (int j = 0; j < TN; j++) acc[i][j] = 0.f;
    int tr = (tid / (BN / TN)) * TM;
    int tc = (tid % (BN / TN)) * TN;

    for (int k0 = 0; k0 < K; k0 += BK) {
        for (int i = tid; i < BM * BK; i += NT) {
            int r = i / BK, k = i % BK;
            int gr = row0 + r, gk = k0 + k;
            float v = 0.f;
            if (gr < M) {
                if (CONCAT)
                    v = (gk < NMUT) ? A[(size_t)gr * NMUT + gk]
                                    : A2[(size_t)gr * D_ + (gk - NMUT)];
                else
                    v = A[(size_t)gr * lda + gk];
            }
            As[r][k] = v;
        }
        for (int i = tid; i < BK * BN; i += NT) {
            int k = i / BN, c = i % BN;
            Bs[k][c] = Bt[(size_t)(k0 + k) * N + col0 + c];
        }
        __syncthreads();
#pragma unroll
        for (int kk = 0; kk < BK; kk++) {
            float ar[TM], br[TN];
#pragma unroll
            for (int i = 0; i < TM; i++) ar[i] = As[tr + i][kk];
#pragma unroll
            for (int j = 0; j < TN; j++) br[j] = Bs[kk][tc + j];
#pragma unroll
            for (int i = 0; i < TM; i++)
#pragma unroll
                for (int j = 0; j < TN; j++)
                    acc[i][j] = fmaf(ar[i], br[j], acc[i][j]);
        }
        __syncthreads();
    }
#pragma unroll
    for (int i = 0; i < TM; i++) {
        int r = row0 + tr + i;
        if (r >= M) break;
#pragma unroll
        for (int j = 0; j < TN; j++) {
            C[(size_t)r * N + col0 + tc + j] = acc[i][j] + bias[col0 + tc + j];
        }
    }
}

// ---------------------------------------------------------------------------
extern "C" void kernel_launch(void* const* d_in, const int* in_sizes, int n_in,
                              void* d_out, int out_size)
{
    const float* features = (const float*)d_in[0];
    const int*   wstarts  = (const int*)d_in[1];
    const float* dense_w  = (const float*)d_in[2];
    const float* dense_b  = (const float*)d_in[3];
    const float* out_w    = (const float*)d_in[4];
    const float* out_b    = (const float*)d_in[5];
    const float* bin_w    = (const float*)d_in[6];
    const float* bin_b    = (const float*)d_in[7];
    (void)in_sizes; (void)n_in; (void)out_size;

    float *wt, *owt, *bwt, *wf, *h;
    cudaGetSymbolAddress((void**)&wt,  g_wt);
    cudaGetSymbolAddress((void**)&owt, g_owt);
    cudaGetSymbolAddress((void**)&bwt, g_bwt);
    cudaGetSymbolAddress((void**)&wf,  g_wf);
    cudaGetSymbolAddress((void**)&h,   g_h);

    float* wcl = (float*)d_out;                         // [M, 64]
    float* bin = (float*)d_out + (size_t)M_ * NMUT;     // [M, 32]

    // 1) segment scan
    scan_kernel<<<B_, 256>>>(wstarts);
    // 2) word features
    wf_kernel<<<M_, 256>>>(features);
    // 3) weight transposes
    {
        dim3 blk(32, 8);
        transpose_kernel<<<dim3(32, 32), blk>>>(dense_w, wt, D_, D_);
        transpose_kernel<<<dim3(32, 2),  blk>>>(out_w,   owt, NMUT, D_);
        transpose_kernel<<<dim3(34, 1),  blk>>>(bin_w,   bwt, NBIN, KCAT);
    }
    // 4) main GEMM + tanh
    gemm_main<<<dim3(8, (M_ + 127) / 128), 256>>>(wf, wt, dense_b, h, M_);
    // 5) class logits: [M,64] = h @ out_w^T + out_b
    gemm_small<64, 64, 16, 4, 4, false><<<dim3(1, (M_ + 63) / 64), 256>>>(
        h, nullptr, owt, out_b, wcl, M_, NMUT, D_, D_);
    // 6) binary logits: [M,32] = cat(wcl, h) @ bin_w^T + bin_b
    gemm_small<64, 32, 16, 4, 4, true><<<dim3(1, (M_ + 63) / 64), 128>>>(
        wcl, h, bwt, bin_b, bin, M_, NBIN, KCAT, 0);
}

// round 4
// speedup vs baseline: 3.3124x; 3.3124x over previous
#include <cuda_runtime.h>
#include <cstdint>

#define B_    16
#define T_    2048
#define D_    1024
#define TT_   2046
#define MW_   682
#define M_    (B_ * MW_)          // 10912
#define MPAD  11008               // 86 * 128
#define NMUT  64
#define NBIN  32
#define NHEAD 96                  // 64 class + 32 binary (fused)

// -------- device scratch (no allocations allowed; zero-initialized) --------
__device__ float g_wf[MPAD * D_];        // word features (padded rows stay 0)
__device__ float g_h [MPAD * D_];        // tanh hidden
__device__ float g_hw[NHEAD * D_];       // fused head weights [96][1024] K-major
__device__ float g_hb[NHEAD];            // fused head bias
__device__ int   g_begin[M_];
__device__ int   g_cnt  [M_];

// ===========================================================================
// helpers
// ===========================================================================
__device__ __forceinline__ uint32_t smem_u32(const void* p) {
    return (uint32_t)__cvta_generic_to_shared(p);
}
__device__ __forceinline__ void cp16(uint32_t dst, const void* src) {
    asm volatile("cp.async.cg.shared.global [%0], [%1], 16;\n" :: "r"(dst), "l"(src));
}
#define CP_COMMIT() asm volatile("cp.async.commit_group;" ::: "memory")

__device__ __forceinline__ uint32_t f2tf(float x) {
    uint32_t r;
    asm("cvt.rna.tf32.f32 %0, %1;" : "=r"(r) : "f"(x));
    return r;
}
__device__ __forceinline__ void mma8(float* c, const uint32_t* a, const uint32_t* b) {
    asm volatile("mma.sync.aligned.m16n8k8.row.col.f32.tf32.tf32.f32 "
        "{%0,%1,%2,%3}, {%4,%5,%6,%7}, {%8,%9}, {%0,%1,%2,%3};"
        : "+f"(c[0]), "+f"(c[1]), "+f"(c[2]), "+f"(c[3])
        : "r"(a[0]), "r"(a[1]), "r"(a[2]), "r"(a[3]), "r"(b[0]), "r"(b[1]));
}

// ===========================================================================
// 1) per-batch scan of word_starts -> word begin token + token count
// ===========================================================================
__global__ void scan_kernel(const int* __restrict__ ws) {
    int b = blockIdx.x;
    const int* w = ws + b * TT_;
    __shared__ int partial[256];
    __shared__ int scnt[MW_];
    int tid = threadIdx.x;
    for (int i = tid; i < MW_; i += 256) scnt[i] = 0;

    int vals[8];
    int s = 0;
#pragma unroll
    for (int i = 0; i < 8; i++) {
        int t = tid * 8 + i;
        int v = (t < TT_) ? w[t] : 0;
        vals[i] = v; s += v;
    }
    partial[tid] = s;
    __syncthreads();
    for (int off = 1; off < 256; off <<= 1) {
        int v = partial[tid];
        int add = (tid >= off) ? partial[tid - off] : 0;
        __syncthreads();
        partial[tid] = v + add;
        __syncthreads();
    }
    int run = (tid > 0) ? partial[tid - 1] : 0;
#pragma unroll
    for (int i = 0; i < 8; i++) {
        int t = tid * 8 + i;
        if (t < TT_) {
            run += vals[i];
            int seg = run - 1;
            if (seg >= 0 && seg < MW_) {
                if (vals[i]) g_begin[b * MW_ + seg] = t;
                atomicAdd(&scnt[seg], 1);
            }
        }
    }
    __syncthreads();
    for (int i = tid; i < MW_; i += 256) g_cnt[b * MW_ + i] = scnt[i];
}

// ===========================================================================
// 2) word-feature segment sums (one block per word)
// ===========================================================================
__global__ void wf_kernel(const float* __restrict__ feat) {
    int m = blockIdx.x;
    int b = m / MW_;
    int tid = threadIdx.x;
    int cnt = g_cnt[m];
    float4* out = (float4*)(g_wf + (size_t)m * D_);
    if (cnt == 0) { out[tid] = make_float4(1.f, 1.f, 1.f, 1.f); return; }
    int t0 = g_begin[m];
    const float4* base = (const float4*)(feat + ((size_t)b * T_ + 1 + t0) * D_);
    float4 acc = base[tid];
    for (int i = 1; i < cnt; i++) {
        float4 v = base[(size_t)i * (D_ / 4) + tid];
        acc.x += v.x; acc.y += v.y; acc.z += v.z; acc.w += v.w;
    }
    out[tid] = acc;
}

// ===========================================================================
// 3) fused head weights:
//    rows 0..63  = out_w                              bias = out_b
//    rows 64..95 = bin_w[:,64:] + bin_w[:,:64]@out_w  bias = bin_b + bin_w[:,:64]@out_b
// ===========================================================================
__global__ void headw_kernel(const float* __restrict__ out_w, const float* __restrict__ out_b,
                             const float* __restrict__ bin_w, const float* __restrict__ bin_b) {
    int r = blockIdx.x;        // 0..95
    int tid = threadIdx.x;     // 256
    if (r < NMUT) {
        const float4* src = (const float4*)(out_w + (size_t)r * D_);
        float4* dst = (float4*)(g_hw + (size_t)r * D_);
        for (int i = tid; i < D_ / 4; i += 256) dst[i] = src[i];
        if (tid == 0) g_hb[r] = out_b[r];
    } else {
        int c = r - NMUT;
        __shared__ float w1[NMUT];
        if (tid < NMUT) w1[tid] = bin_w[(size_t)c * (D_ + NMUT) + tid];
        __syncthreads();
        for (int i = tid; i < D_; i += 256) {
            float acc = bin_w[(size_t)c * (D_ + NMUT) + NMUT + i];
#pragma unroll 8
            for (int j = 0; j < NMUT; j++) acc += w1[j] * out_w[(size_t)j * D_ + i];
            g_hw[(size_t)r * D_ + i] = acc;
        }
        if (tid == 0) {
            float bb = bin_b[c];
            for (int j = 0; j < NMUT; j++) bb += w1[j] * out_b[j];
            g_hb[r] = bb;
        }
    }
}

// ===========================================================================
// 4) tf32 mma.sync GEMM:  D[128 x BN] = A[128 x 1024] @ B[BN x 1024]^T
//    BK=16, cp.async double buffer, 8 warps (4m x 2n), warp tile 32 x BN/2.
//    TANH=true : O1 = tanh(D + bias), row stride 1024 (writes padded rows too)
//    TANH=false: split heads: col<64 -> O1 (stride 64), col>=64 -> O2 (stride 32)
// ===========================================================================
template<int BN, bool TANH>
__global__ __launch_bounds__(256) void tc_gemm(
    const float* __restrict__ A, const float* __restrict__ Bw,
    const float* __restrict__ bias,
    float* __restrict__ O1, float* __restrict__ O2, int Mlim)
{
    constexpr int NF = BN / 16;            // n-tiles (of 8) per warp
    __shared__ float As[2][128][20];       // stride 20: conflict-free frag loads
    __shared__ float Bs[2][BN][20];

    const int tid = threadIdx.x;
    const int lane = tid & 31, wid = tid >> 5;
    const int g = lane >> 2, tg = lane & 3;        // groupID, thread-in-group
    const int wm = (wid & 3) * 32;                 // warp m offset in tile
    const int wn = (wid >> 2) * (BN / 2);          // warp n offset in tile
    const int row0 = blockIdx.y * 128;
    const int col0 = blockIdx.x * BN;

    float acc[2][NF][4];
#pragma unroll
    for (int i = 0; i < 2; i++)
#pragma unroll
        for (int j = 0; j < NF; j++)
#pragma unroll
            for (int q = 0; q < 4; q++) acc[i][j][q] = 0.f;

    const float* Ab = A + (size_t)row0 * D_;
    const float* Bb = Bw + (size_t)col0 * D_;

    auto loadA = [&](int buf, int k0) {
#pragma unroll
        for (int i = tid; i < 512; i += 256) {
            int r = i >> 2, c = i & 3;
            cp16(smem_u32(&As[buf][r][c * 4]), Ab + (size_t)r * D_ + k0 + c * 4);
        }
    };
    auto loadB = [&](int buf, int k0) {
        for (int i = tid; i < BN * 4; i += 256) {
            int r = i >> 2, c = i & 3;
            cp16(smem_u32(&Bs[buf][r][c * 4]), Bb + (size_t)r * D_ + k0 + c * 4);
        }
    };
    auto compute = [&](int buf) {
#pragma unroll
        for (int ks = 0; ks < 2; ks++) {
            const int kk = ks * 8;
            uint32_t a[2][4];
#pragma unroll
            for (int i = 0; i < 2; i++) {
                int r = wm + i * 16 + g;
                a[i][0] = f2tf(As[buf][r][kk + tg]);
                a[i][1] = f2tf(As[buf][r + 8][kk + tg]);
                a[i][2] = f2tf(As[buf][r][kk + tg + 4]);
                a[i][3] = f2tf(As[buf][r + 8][kk + tg + 4]);
            }
#pragma unroll
            for (int j = 0; j < NF; j++) {
                int n = wn + j * 8 + g;
                uint32_t b[2];
                b[0] = f2tf(Bs[buf][n][kk + tg]);
                b[1] = f2tf(Bs[buf][n][kk + tg + 4]);
                mma8(acc[0][j], a[0], b);
                mma8(acc[1][j], a[1], b);
            }
        }
    };

    // pipeline
    loadA(0, 0); loadB(0, 0); CP_COMMIT();
    int buf = 0;
    for (int k0 = 0; k0 < D_; k0 += 16) {
        if (k0 + 16 < D_) {
            loadA(buf ^ 1, k0 + 16);
            loadB(buf ^ 1, k0 + 16);
            CP_COMMIT();
            asm volatile("cp.async.wait_group 1;" ::: "memory");
        } else {
            asm volatile("cp.async.wait_group 0;" ::: "memory");
        }
        __syncthreads();
        compute(buf);
        __syncthreads();          // all warps done with buf before it is reloaded
        buf ^= 1;
    }

    // ---- epilogue ----
#pragma unroll
    for (int i = 0; i < 2; i++) {
#pragma unroll
        for (int j = 0; j < NF; j++) {
            int r = row0 + wm + i * 16 + g;
            int c = col0 + wn + j * 8 + tg * 2;
            if (TANH) {
                float2 v0, v1;
                v0.x = tanhf(acc[i][j][0] + bias[c]);
                v0.y = tanhf(acc[i][j][1] + bias[c + 1]);
                v1.x = tanhf(acc[i][j][2] + bias[c]);
                v1.y = tanhf(acc[i][j][3] + bias[c + 1]);
                *(float2*)(O1 + (size_t)r * D_ + c) = v0;
                *(float2*)(O1 + (size_t)(r + 8) * D_ + c) = v1;
            } else {
#pragma unroll
                for (int rr = 0; rr < 2; rr++) {
                    int row = r + rr * 8;
                    if (row < Mlim) {
                        float x0 = acc[i][j][rr * 2 + 0] + bias[c];
                        float x1 = acc[i][j][rr * 2 + 1] + bias[c + 1];
                        if (c < NMUT) {
                            O1[(size_t)row * NMUT + c] = x0;
                            O1[(size_t)row * NMUT + c + 1] = x1;
                        } else {
                            O2[(size_t)row * NBIN + (c - NMUT)] = x0;
                            O2[(size_t)row * NBIN + (c - NMUT) + 1] = x1;
                        }
                    }
                }
            }
        }
    }
}

// ===========================================================================
extern "C" void kernel_launch(void* const* d_in, const int* in_sizes, int n_in,
                              void* d_out, int out_size)
{
    const float* features = (const float*)d_in[0];
    const int*   wstarts  = (const int*)d_in[1];
    const float* dense_w  = (const float*)d_in[2];
    const float* dense_b  = (const float*)d_in[3];
    const float* out_w    = (const float*)d_in[4];
    const float* out_b    = (const float*)d_in[5];
    const float* bin_w    = (const float*)d_in[6];
    const float* bin_b    = (const float*)d_in[7];
    (void)in_sizes; (void)n_in; (void)out_size;

    float *wf, *h, *hw, *hb;
    cudaGetSymbolAddress((void**)&wf, g_wf);
    cudaGetSymbolAddress((void**)&h,  g_h);
    cudaGetSymbolAddress((void**)&hw, g_hw);
    cudaGetSymbolAddress((void**)&hb, g_hb);

    float* wcl = (float*)d_out;                        // [M, 64]
    float* bin = (float*)d_out + (size_t)M_ * NMUT;    // [M, 32]

    scan_kernel<<<B_, 256>>>(wstarts);
    wf_kernel<<<M_, 256>>>(features);
    headw_kernel<<<NHEAD, 256>>>(out_w, out_b, bin_w, bin_b);

    // h = tanh(wf @ dense_w^T + dense_b)
    tc_gemm<128, true><<<dim3(8, MPAD / 128), 256>>>(
        wf, dense_w, dense_b, h, nullptr, MPAD);
    // [wcl | bin] = h @ g_hw^T + g_hb
    tc_gemm<96, false><<<dim3(1, MPAD / 128), 256>>>(
        h, hw, hb, wcl, bin, M_);
}

// round 5
// speedup vs baseline: 3.5821x; 1.0814x over previous
#include <cuda_runtime.h>
#include <cstdint>

#define B_    16
#define T_    2048
#define D_    1024
#define TT_   2046
#define MW_   682
#define M_    (B_ * MW_)          // 10912
#define MPAD  11008               // 86 * 128
#define NMUT  64
#define NBIN  32
#define NHEAD 96                  // 64 class + 32 binary (fused)

// -------- device scratch (no allocations allowed; zero-initialized) --------
__device__ float g_wf[MPAD * D_];        // word features, tf32-rounded
__device__ float g_h [MPAD * D_];        // tanh hidden, tf32-rounded
__device__ float g_wt[D_ * D_];          // dense_w, tf32-rounded
__device__ float g_hw[NHEAD * D_];       // fused head weights, tf32-rounded
__device__ float g_hb[NHEAD];            // fused head bias
__device__ int   g_begin[M_];
__device__ int   g_cnt  [M_];

// ===========================================================================
// helpers
// ===========================================================================
__device__ __forceinline__ uint32_t smem_u32(const void* p) {
    return (uint32_t)__cvta_generic_to_shared(p);
}
__device__ __forceinline__ void cp16(uint32_t dst, const void* src) {
    asm volatile("cp.async.cg.shared.global [%0], [%1], 16;\n" :: "r"(dst), "l"(src));
}
#define CP_COMMIT() asm volatile("cp.async.commit_group;" ::: "memory")

__device__ __forceinline__ float f2tf(float x) {
    uint32_t r;
    asm("cvt.rna.tf32.f32 %0, %1;" : "=r"(r) : "f"(x));
    return __uint_as_float(r);
}
__device__ __forceinline__ void mma8(float* c, const uint32_t* a, const uint32_t* b) {
    asm volatile("mma.sync.aligned.m16n8k8.row.col.f32.tf32.tf32.f32 "
        "{%0,%1,%2,%3}, {%4,%5,%6,%7}, {%8,%9}, {%0,%1,%2,%3};"
        : "+f"(c[0]), "+f"(c[1]), "+f"(c[2]), "+f"(c[3])
        : "r"(a[0]), "r"(a[1]), "r"(a[2]), "r"(a[3]), "r"(b[0]), "r"(b[1]));
}

// ===========================================================================
// 1) per-batch scan of word_starts -> word begin token + token count
// ===========================================================================
__global__ void scan_kernel(const int* __restrict__ ws) {
    int b = blockIdx.x;
    const int* w = ws + b * TT_;
    __shared__ int partial[256];
    __shared__ int scnt[MW_];
    int tid = threadIdx.x;
    for (int i = tid; i < MW_; i += 256) scnt[i] = 0;

    int vals[8];
    int s = 0;
#pragma unroll
    for (int i = 0; i < 8; i++) {
        int t = tid * 8 + i;
        int v = (t < TT_) ? w[t] : 0;
        vals[i] = v; s += v;
    }
    partial[tid] = s;
    __syncthreads();
    for (int off = 1; off < 256; off <<= 1) {
        int v = partial[tid];
        int add = (tid >= off) ? partial[tid - off] : 0;
        __syncthreads();
        partial[tid] = v + add;
        __syncthreads();
    }
    int run = (tid > 0) ? partial[tid - 1] : 0;
#pragma unroll
    for (int i = 0; i < 8; i++) {
        int t = tid * 8 + i;
        if (t < TT_) {
            run += vals[i];
            int seg = run - 1;
            if (seg >= 0 && seg < MW_) {
                if (vals[i]) g_begin[b * MW_ + seg] = t;
                atomicAdd(&scnt[seg], 1);
            }
        }
    }
    __syncthreads();
    for (int i = tid; i < MW_; i += 256) g_cnt[b * MW_ + i] = scnt[i];
}

// ===========================================================================
// 2) word-feature segment sums (one block per word), tf32-rounded output
// ===========================================================================
__global__ void wf_kernel(const float* __restrict__ feat) {
    int m = blockIdx.x;
    int b = m / MW_;
    int tid = threadIdx.x;
    int cnt = g_cnt[m];
    float4* out = (float4*)(g_wf + (size_t)m * D_);
    if (cnt == 0) {
        float one = f2tf(1.f);
        out[tid] = make_float4(one, one, one, one);
        return;
    }
    int t0 = g_begin[m];
    const float4* base = (const float4*)(feat + ((size_t)b * T_ + 1 + t0) * D_);
    float4 acc = base[tid];
    for (int i = 1; i < cnt; i++) {
        float4 v = base[(size_t)i * (D_ / 4) + tid];
        acc.x += v.x; acc.y += v.y; acc.z += v.z; acc.w += v.w;
    }
    acc.x = f2tf(acc.x); acc.y = f2tf(acc.y);
    acc.z = f2tf(acc.z); acc.w = f2tf(acc.w);
    out[tid] = acc;
}

// ===========================================================================
// 2b) tf32 round-copy of dense_w
// ===========================================================================
__global__ void roundw_kernel(const float* __restrict__ src) {
    int i = blockIdx.x * 256 + threadIdx.x;     // float4 index
    float4 v = ((const float4*)src)[i];
    v.x = f2tf(v.x); v.y = f2tf(v.y); v.z = f2tf(v.z); v.w = f2tf(v.w);
    ((float4*)g_wt)[i] = v;
}

// ===========================================================================
// 3) fused head weights (tf32-rounded):
//    rows 0..63  = out_w                              bias = out_b
//    rows 64..95 = bin_w[:,64:] + bin_w[:,:64]@out_w  bias = bin_b + bin_w[:,:64]@out_b
// ===========================================================================
__global__ void headw_kernel(const float* __restrict__ out_w, const float* __restrict__ out_b,
                             const float* __restrict__ bin_w, const float* __restrict__ bin_b) {
    int r = blockIdx.x;        // 0..95
    int tid = threadIdx.x;     // 256
    if (r < NMUT) {
        const float* src = out_w + (size_t)r * D_;
        float* dst = g_hw + (size_t)r * D_;
        for (int i = tid; i < D_; i += 256) dst[i] = f2tf(src[i]);
        if (tid == 0) g_hb[r] = out_b[r];
    } else {
        int c = r - NMUT;
        __shared__ float w1[NMUT];
        if (tid < NMUT) w1[tid] = bin_w[(size_t)c * (D_ + NMUT) + tid];
        __syncthreads();
        for (int i = tid; i < D_; i += 256) {
            float acc = bin_w[(size_t)c * (D_ + NMUT) + NMUT + i];
#pragma unroll 8
            for (int j = 0; j < NMUT; j++) acc += w1[j] * out_w[(size_t)j * D_ + i];
            g_hw[(size_t)r * D_ + i] = f2tf(acc);
        }
        if (tid == 0) {
            float bb = bin_b[c];
            for (int j = 0; j < NMUT; j++) bb += w1[j] * out_b[j];
            g_hb[r] = bb;
        }
    }
}

// ===========================================================================
// 4) tf32 mma.sync GEMM:  D[128 x BN] = A[128 x 1024] @ B[BN x 1024]^T
//    BK=16, 3-stage cp.async pipeline (1 barrier/iter), inputs pre-rounded.
//    8 warps (4m x 2n), warp tile 32 x BN/2.
// ===========================================================================
template<int BN, bool TANH>
__global__ __launch_bounds__(256) void tc_gemm(
    const float* __restrict__ A, const float* __restrict__ Bw,
    const float* __restrict__ bias,
    float* __restrict__ O1, float* __restrict__ O2, int Mlim)
{
    constexpr int NF = BN / 16;                 // n-frags per warp
    constexpr int AST = 128 * 20;               // floats per A stage
    constexpr int BST = BN * 20;                // floats per B stage
    extern __shared__ float smem[];
    float* Asm = smem;                          // [3][128][20]
    float* Bsm = smem + 3 * AST;                // [3][BN][20]

    const int tid = threadIdx.x;
    const int lane = tid & 31, wid = tid >> 5;
    const int g = lane >> 2, tg = lane & 3;
    const int wm = (wid & 3) * 32;
    const int wn = (wid >> 2) * (BN / 2);
    const int row0 = blockIdx.y * 128;
    const int col0 = blockIdx.x * BN;

    float acc[2][NF][4];
#pragma unroll
    for (int i = 0; i < 2; i++)
#pragma unroll
        for (int j = 0; j < NF; j++)
#pragma unroll
            for (int q = 0; q < 4; q++) acc[i][j][q] = 0.f;

    const float* Ab = A + (size_t)row0 * D_;
    const float* Bb = Bw + (size_t)col0 * D_;

    auto loadStage = [&](int st, int k0) {
        float* Ad = Asm + st * AST;
#pragma unroll
        for (int i = tid; i < 512; i += 256) {
            int r = i >> 2, c = i & 3;
            cp16(smem_u32(Ad + r * 20 + c * 4), Ab + (size_t)r * D_ + k0 + c * 4);
        }
        float* Bd = Bsm + st * BST;
        for (int i = tid; i < BN * 4; i += 256) {
            int r = i >> 2, c = i & 3;
            cp16(smem_u32(Bd + r * 20 + c * 4), Bb + (size_t)r * D_ + k0 + c * 4);
        }
        CP_COMMIT();
    };
    auto compute = [&](int st) {
        const float* Ad = Asm + st * AST;
        const float* Bd = Bsm + st * BST;
#pragma unroll
        for (int ks = 0; ks < 2; ks++) {
            const int kk = ks * 8;
            uint32_t a[2][4];
#pragma unroll
            for (int i = 0; i < 2; i++) {
                const float* ap = Ad + (wm + i * 16 + g) * 20 + kk + tg;
                a[i][0] = __float_as_uint(ap[0]);
                a[i][1] = __float_as_uint(ap[8 * 20]);
                a[i][2] = __float_as_uint(ap[4]);
                a[i][3] = __float_as_uint(ap[8 * 20 + 4]);
            }
#pragma unroll
            for (int j = 0; j < NF; j++) {
                const float* bp = Bd + (wn + j * 8 + g) * 20 + kk + tg;
                uint32_t b[2];
                b[0] = __float_as_uint(bp[0]);
                b[1] = __float_as_uint(bp[4]);
                mma8(acc[0][j], a[0], b);
                mma8(acc[1][j], a[1], b);
            }
        }
    };

    // 3-stage pipeline, one barrier per iteration
    loadStage(0, 0);
    loadStage(1, 16);
    int st = 0;
    for (int k0 = 0; k0 < D_; k0 += 16) {
        asm volatile("cp.async.wait_group 1;" ::: "memory");
        __syncthreads();
        if (k0 + 32 < D_) {
            int nst = st + 2; if (nst >= 3) nst -= 3;
            loadStage(nst, k0 + 32);
        }
        compute(st);
        st = (st == 2) ? 0 : st + 1;
    }

    // ---- epilogue ----
#pragma unroll
    for (int i = 0; i < 2; i++) {
#pragma unroll
        for (int j = 0; j < NF; j++) {
            int r = row0 + wm + i * 16 + g;
            int c = col0 + wn + j * 8 + tg * 2;
            if (TANH) {
                float2 v0, v1;
                v0.x = f2tf(tanhf(acc[i][j][0] + bias[c]));
                v0.y = f2tf(tanhf(acc[i][j][1] + bias[c + 1]));
                v1.x = f2tf(tanhf(acc[i][j][2] + bias[c]));
                v1.y = f2tf(tanhf(acc[i][j][3] + bias[c + 1]));
                *(float2*)(O1 + (size_t)r * D_ + c) = v0;
                *(float2*)(O1 + (size_t)(r + 8) * D_ + c) = v1;
            } else {
#pragma unroll
                for (int rr = 0; rr < 2; rr++) {
                    int row = r + rr * 8;
                    if (row < Mlim) {
                        float x0 = acc[i][j][rr * 2 + 0] + bias[c];
                        float x1 = acc[i][j][rr * 2 + 1] + bias[c + 1];
                        if (c < NMUT) {
                            O1[(size_t)row * NMUT + c] = x0;
                            O1[(size_t)row * NMUT + c + 1] = x1;
                        } else {
                            O2[(size_t)row * NBIN + (c - NMUT)] = x0;
                            O2[(size_t)row * NBIN + (c - NMUT) + 1] = x1;
                        }
                    }
                }
            }
        }
    }
}

// ===========================================================================
extern "C" void kernel_launch(void* const* d_in, const int* in_sizes, int n_in,
                              void* d_out, int out_size)
{
    const float* features = (const float*)d_in[0];
    const int*   wstarts  = (const int*)d_in[1];
    const float* dense_w  = (const float*)d_in[2];
    const float* dense_b  = (const float*)d_in[3];
    const float* out_w    = (const float*)d_in[4];
    const float* out_b    = (const float*)d_in[5];
    const float* bin_w    = (const float*)d_in[6];
    const float* bin_b    = (const float*)d_in[7];
    (void)in_sizes; (void)n_in; (void)out_size;

    float *wf, *h, *wt, *hw, *hb;
    cudaGetSymbolAddress((void**)&wf, g_wf);
    cudaGetSymbolAddress((void**)&h,  g_h);
    cudaGetSymbolAddress((void**)&wt, g_wt);
    cudaGetSymbolAddress((void**)&hw, g_hw);
    cudaGetSymbolAddress((void**)&hb, g_hb);

    float* wcl = (float*)d_out;                        // [M, 64]
    float* bin = (float*)d_out + (size_t)M_ * NMUT;    // [M, 32]

    const int SMEM_MAIN = 3 * (128 * 20 + 128 * 20) * 4;   // 61440
    const int SMEM_HEAD = 3 * (128 * 20 + 96 * 20) * 4;    // 53760
    cudaFuncSetAttribute(tc_gemm<128, true>,
                         cudaFuncAttributeMaxDynamicSharedMemorySize, SMEM_MAIN);
    cudaFuncSetAttribute(tc_gemm<96, false>,
                         cudaFuncAttributeMaxDynamicSharedMemorySize, SMEM_HEAD);

    scan_kernel<<<B_, 256>>>(wstarts);
    wf_kernel<<<M_, 256>>>(features);
    roundw_kernel<<<D_ * D_ / 4 / 256, 256>>>(dense_w);
    headw_kernel<<<NHEAD, 256>>>(out_w, out_b, bin_w, bin_b);

    // h = tanh(wf @ dense_w^T + dense_b)
    tc_gemm<128, true><<<dim3(8, MPAD / 128), 256, SMEM_MAIN>>>(
        wf, wt, dense_b, h, nullptr, MPAD);
    // [wcl | bin] = h @ g_hw^T + g_hb
    tc_gemm<96, false><<<dim3(1, MPAD / 128), 256, SMEM_HEAD>>>(
        h, hw, hb, wcl, bin, M_);
}